// round 4
// baseline (speedup 1.0000x reference)
#include <cuda_runtime.h>
#include <math.h>

#define LSE_EPS 1e-5f
#define WPB 8   // warps per block (256 threads)

__global__ __launch_bounds__(256) void lse_halfpair_kernel(
    const float* __restrict__ coords,        // (BN, 3)
    const float* __restrict__ nbr,           // (BN, 16, 3)
    const float* __restrict__ W1, const float* __restrict__ g1,
    const float* __restrict__ b1, const float* __restrict__ m1,
    const float* __restrict__ v1,
    const float* __restrict__ W2, const float* __restrict__ g2,
    const float* __restrict__ b2, const float* __restrict__ m2,
    const float* __restrict__ v2,
    float* __restrict__ out,                 // (BN, 16, 8)
    int total_bnk)                           // BN * 16
{
    __shared__ float sw[64];                         // folded weights
    __shared__ __align__(16) float cc[WPB][12];      // 4 center coords per warp

    int tid = threadIdx.x;

    // In-block BN fold
    if (tid < 4) {
        float s = g1[tid] * rsqrtf(v1[tid] + LSE_EPS);
        sw[16 + tid] = b1[tid] - m1[tid] * s;
        #pragma unroll
        for (int c = 0; c < 4; ++c) sw[tid * 4 + c] = W1[tid * 4 + c] * s;
    } else if (tid < 12) {
        int j = tid - 4;
        float s = g2[j] * rsqrtf(v2[j] + LSE_EPS);
        sw[52 + j] = b2[j] - m2[j] * s;
        #pragma unroll
        for (int c = 0; c < 4; ++c) sw[20 + j * 4 + c] = W2[j * 4 + c] * s;
    }
    __syncthreads();

    int warp = tid >> 5;
    int lane = tid & 31;
    long long Wg = (long long)blockIdx.x * WPB + warp;   // global warp id
    long long P0 = Wg * 64;                              // warp's first pair
    int q   = lane >> 1;       // pair-slot within bn (0..15)
    int par = lane & 1;        // which output half this lane produces

    if (P0 + 64 <= (long long)total_bnk) {
        // Stage this warp's 4 center coords (12 floats, 16B aligned) into SMEM
        if (lane < 3) {
            reinterpret_cast<float4*>(cc[warp])[lane] =
                reinterpret_cast<const float4*>(coords)[Wg * 3 + lane];
        }
        __syncwarp();

        // Weights to registers: full layer1, parity-half of layer2
        float fw1[16], fb1[4], fw2[16], fb2[4];
        #pragma unroll
        for (int i = 0; i < 16; ++i) fw1[i] = sw[i];
        #pragma unroll
        for (int i = 0; i < 4;  ++i) fb1[i] = sw[16 + i];
        #pragma unroll
        for (int i = 0; i < 16; ++i) fw2[i] = sw[20 + par * 16 + i];
        #pragma unroll
        for (int i = 0; i < 4;  ++i) fb2[i] = sw[52 + par * 4 + i];

        // Front-batched neighbor loads: 12 independent LDGs in flight (MLP=12)
        float nx[4], ny[4], nz[4];
        #pragma unroll
        for (int i = 0; i < 4; ++i) {
            const float* np = nbr + (P0 + q + 16 * i) * 3;
            nx[i] = np[0]; ny[i] = np[1]; nz[i] = np[2];
        }

        float4* ob = reinterpret_cast<float4*>(out) + P0 * 2;

        #pragma unroll
        for (int i = 0; i < 4; ++i) {
            float cx = cc[warp][3 * i + 0];
            float cy = cc[warp][3 * i + 1];
            float cz = cc[warp][3 * i + 2];
            float rx = nx[i] - cx, ry = ny[i] - cy, rz = nz[i] - cz;
            float dist = sqrtf(fmaf(rx, rx, fmaf(ry, ry, rz * rz)));

            float h[4];
            #pragma unroll
            for (int o = 0; o < 4; ++o) {
                float acc = fb1[o];
                acc = fmaf(fw1[o * 4 + 0], rx, acc);
                acc = fmaf(fw1[o * 4 + 1], ry, acc);
                acc = fmaf(fw1[o * 4 + 2], rz, acc);
                acc = fmaf(fw1[o * 4 + 3], dist, acc);
                h[o] = fmaxf(acc, 0.0f);
            }

            float o4[4];
            #pragma unroll
            for (int j = 0; j < 4; ++j) {
                float acc = fb2[j];
                acc = fmaf(fw2[j * 4 + 0], h[0], acc);
                acc = fmaf(fw2[j * 4 + 1], h[1], acc);
                acc = fmaf(fw2[j * 4 + 2], h[2], acc);
                acc = fmaf(fw2[j * 4 + 3], h[3], acc);
                o4[j] = fmaxf(acc, 0.0f);
            }

            // float4 index = 2*P0 + lane + 32*i  -> perfectly coalesced
            ob[lane + 32 * i] = make_float4(o4[0], o4[1], o4[2], o4[3]);
        }
    } else {
        // Tail (not exercised for B=8,N=16384,K=16)
        #pragma unroll
        for (int i = 0; i < 4; ++i) {
            long long p = P0 + q + 16 * i;
            if (p >= (long long)total_bnk) continue;
            long long bn = p >> 4;
            float rx = nbr[p * 3 + 0] - coords[bn * 3 + 0];
            float ry = nbr[p * 3 + 1] - coords[bn * 3 + 1];
            float rz = nbr[p * 3 + 2] - coords[bn * 3 + 2];
            float dist = sqrtf(fmaf(rx, rx, fmaf(ry, ry, rz * rz)));
            float h[4];
            #pragma unroll
            for (int o = 0; o < 4; ++o) {
                float acc = sw[16 + o];
                acc = fmaf(sw[o * 4 + 0], rx, acc);
                acc = fmaf(sw[o * 4 + 1], ry, acc);
                acc = fmaf(sw[o * 4 + 2], rz, acc);
                acc = fmaf(sw[o * 4 + 3], dist, acc);
                h[o] = fmaxf(acc, 0.0f);
            }
            #pragma unroll
            for (int j = 0; j < 4; ++j) {
                int jj = par * 4 + j;
                float acc = sw[52 + jj];
                acc = fmaf(sw[20 + jj * 4 + 0], h[0], acc);
                acc = fmaf(sw[20 + jj * 4 + 1], h[1], acc);
                acc = fmaf(sw[20 + jj * 4 + 2], h[2], acc);
                acc = fmaf(sw[20 + jj * 4 + 3], h[3], acc);
                out[p * 8 + jj] = fmaxf(acc, 0.0f);
            }
        }
    }
}

extern "C" void kernel_launch(void* const* d_in, const int* in_sizes, int n_in,
                              void* d_out, int out_size)
{
    const float* coords = (const float*)d_in[0];
    const float* nbr    = (const float*)d_in[1];
    const float* W1 = (const float*)d_in[2];
    const float* g1 = (const float*)d_in[3];
    const float* b1 = (const float*)d_in[4];
    const float* m1 = (const float*)d_in[5];
    const float* v1 = (const float*)d_in[6];
    const float* W2 = (const float*)d_in[7];
    const float* g2 = (const float*)d_in[8];
    const float* b2 = (const float*)d_in[9];
    const float* m2 = (const float*)d_in[10];
    const float* v2 = (const float*)d_in[11];
    float* out = (float*)d_out;

    int total_bn  = in_sizes[0] / 3;
    int total_bnk = total_bn * 16;
    int pairs_per_block = 64 * WPB;   // 512
    int grid = (total_bnk + pairs_per_block - 1) / pairs_per_block;

    lse_halfpair_kernel<<<grid, 256>>>(coords, nbr,
                                       W1, g1, b1, m1, v1,
                                       W2, g2, b2, m2, v2,
                                       out, total_bnk);
}

// round 5
// speedup vs baseline: 1.4608x; 1.4608x over previous
#include <cuda_runtime.h>
#include <math.h>
#include <stdint.h>

#define LSE_EPS 1e-5f
#define WPB 8                 // warps per block (256 threads)
#define NBLOCKS 592           // 4 * 148 SMs, persistent
#define STAGE_FLOATS 204      // 192 nbr floats + 12 coord floats per 64-pair chunk

__device__ __forceinline__ void cp16(uint32_t dst, const void* src) {
    asm volatile("cp.async.ca.shared.global [%0], [%1], 16;" :: "r"(dst), "l"(src));
}
__device__ __forceinline__ void cp_commit() {
    asm volatile("cp.async.commit_group;" ::: "memory");
}
__device__ __forceinline__ void cp_wait1() {
    asm volatile("cp.async.wait_group 1;" ::: "memory");
}

__global__ __launch_bounds__(256) void lse_persist_kernel(
    const float* __restrict__ coords,        // (BN, 3)
    const float* __restrict__ nbr,           // (BN, 16, 3)
    const float* __restrict__ W1, const float* __restrict__ g1,
    const float* __restrict__ b1, const float* __restrict__ m1,
    const float* __restrict__ v1,
    const float* __restrict__ W2, const float* __restrict__ g2,
    const float* __restrict__ b2, const float* __restrict__ m2,
    const float* __restrict__ v2,
    float* __restrict__ out,                 // (BN, 16, 8)
    int total_bnk)
{
    __shared__ float sw[64];
    __shared__ __align__(16) float sbuf[WPB][2][STAGE_FLOATS];

    int tid = threadIdx.x;

    // BN fold (once per block)
    if (tid < 4) {
        float s = g1[tid] * rsqrtf(v1[tid] + LSE_EPS);
        sw[16 + tid] = b1[tid] - m1[tid] * s;
        #pragma unroll
        for (int c = 0; c < 4; ++c) sw[tid * 4 + c] = W1[tid * 4 + c] * s;
    } else if (tid < 12) {
        int j = tid - 4;
        float s = g2[j] * rsqrtf(v2[j] + LSE_EPS);
        sw[52 + j] = b2[j] - m2[j] * s;
        #pragma unroll
        for (int c = 0; c < 4; ++c) sw[20 + j * 4 + c] = W2[j * 4 + c] * s;
    }
    __syncthreads();

    int warp = tid >> 5;
    int lane = tid & 31;
    int q    = lane >> 1;     // pair slot (0..15)
    int par  = lane & 1;      // output half / layer1 half owned by this lane

    long long nchunk = (long long)(total_bnk >> 6);     // full 64-pair chunks
    long long wgid   = (long long)blockIdx.x * WPB + warp;
    long long nwarps = (long long)NBLOCKS * WPB;

    // ---- Stage weights ONCE per warp (parity-split) ----
    // layer1: rows 2par, 2par+1
    float fw1h[8], fb1h[2];
    #pragma unroll
    for (int rr = 0; rr < 2; ++rr) {
        fb1h[rr] = sw[16 + 2 * par + rr];
        #pragma unroll
        for (int c = 0; c < 4; ++c) fw1h[rr * 4 + c] = sw[(2 * par + rr) * 4 + c];
    }
    // layer2: rows par*4..par*4+3, columns permuted to {own0, own1, oth0, oth1}
    float fw2[16], fb2[4];
    #pragma unroll
    for (int j = 0; j < 4; ++j) {
        int jr = par * 4 + j;
        fb2[j] = sw[52 + jr];
        fw2[j * 4 + 0] = sw[20 + jr * 4 + 2 * par];
        fw2[j * 4 + 1] = sw[20 + jr * 4 + 2 * par + 1];
        fw2[j * 4 + 2] = sw[20 + jr * 4 + 2 - 2 * par];
        fw2[j * 4 + 3] = sw[20 + jr * 4 + 3 - 2 * par];
    }

    const float4* nbr4 = reinterpret_cast<const float4*>(nbr);
    const float4* crd4 = reinterpret_cast<const float4*>(coords);
    float4* out4 = reinterpret_cast<float4*>(out);

    // per-warp double-buffered staging
    uint32_t sb0 = (uint32_t)__cvta_generic_to_shared(&sbuf[warp][0][0]);
    uint32_t sb1 = (uint32_t)__cvta_generic_to_shared(&sbuf[warp][1][0]);

    // prefetch helper (manually inlined via lambda)
    auto prefetch = [&](long long c, uint32_t sb) {
        const float4* ns = nbr4 + c * 48;
        const float4* cs = crd4 + c * 3;
        cp16(sb + lane * 16, ns + lane);
        if (lane < 16) cp16(sb + (32 + lane) * 16, ns + 32 + lane);
        if (lane >= 29) cp16(sb + 768 + (lane - 29) * 16, cs + (lane - 29));
        cp_commit();
    };

    long long c = wgid;
    int buf = 0;
    if (c < nchunk) prefetch(c, sb0); else cp_commit();

    while (c < nchunk) {
        long long cn = c + nwarps;
        prefetch(cn < nchunk ? cn : wgid, buf ? sb0 : sb1);   // clamped: data unused if OOB
        cp_wait1();
        __syncwarp();

        const float* in = &sbuf[warp][buf][0];
        // coords: 12 floats as 3 broadcast float4 reads
        float4 c40 = reinterpret_cast<const float4*>(in + 192)[0];
        float4 c41 = reinterpret_cast<const float4*>(in + 192)[1];
        float4 c42 = reinterpret_cast<const float4*>(in + 192)[2];
        float ccf[12] = { c40.x, c40.y, c40.z, c40.w, c41.x, c41.y, c41.z, c41.w,
                          c42.x, c42.y, c42.z, c42.w };

        float4* ob = out4 + c * 128;

        #pragma unroll
        for (int i = 0; i < 4; ++i) {
            int nb = 3 * (q + 16 * i);
            float rx = in[nb + 0] - ccf[3 * i + 0];
            float ry = in[nb + 1] - ccf[3 * i + 1];
            float rz = in[nb + 2] - ccf[3 * i + 2];
            float dist = sqrtf(fmaf(rx, rx, fmaf(ry, ry, rz * rz)));

            // layer1: this lane computes its 2 rows; partner computes the other 2
            float own0 = fb1h[0];
            own0 = fmaf(fw1h[0], rx, own0);
            own0 = fmaf(fw1h[1], ry, own0);
            own0 = fmaf(fw1h[2], rz, own0);
            own0 = fmaf(fw1h[3], dist, own0);
            own0 = fmaxf(own0, 0.0f);
            float own1 = fb1h[1];
            own1 = fmaf(fw1h[4], rx, own1);
            own1 = fmaf(fw1h[5], ry, own1);
            own1 = fmaf(fw1h[6], rz, own1);
            own1 = fmaf(fw1h[7], dist, own1);
            own1 = fmaxf(own1, 0.0f);

            float oth0 = __shfl_xor_sync(0xffffffffu, own0, 1);
            float oth1 = __shfl_xor_sync(0xffffffffu, own1, 1);

            float o4[4];
            #pragma unroll
            for (int j = 0; j < 4; ++j) {
                float acc = fb2[j];
                acc = fmaf(fw2[j * 4 + 0], own0, acc);
                acc = fmaf(fw2[j * 4 + 1], own1, acc);
                acc = fmaf(fw2[j * 4 + 2], oth0, acc);
                acc = fmaf(fw2[j * 4 + 3], oth1, acc);
                o4[j] = fmaxf(acc, 0.0f);
            }

            ob[lane + 32 * i] = make_float4(o4[0], o4[1], o4[2], o4[3]);
        }
        __syncwarp();   // all lanes done reading buf before next prefetch overwrites it
        buf ^= 1;
        c += nwarps;
    }

    // ---- Remainder pairs (total_bnk % 64); not exercised for this shape ----
    long long rem_start = nchunk << 6;
    long long gid = (long long)blockIdx.x * blockDim.x + tid;
    long long p = rem_start + gid;
    if (p < (long long)total_bnk) {
        long long bn = p >> 4;
        float rx = nbr[p * 3 + 0] - coords[bn * 3 + 0];
        float ry = nbr[p * 3 + 1] - coords[bn * 3 + 1];
        float rz = nbr[p * 3 + 2] - coords[bn * 3 + 2];
        float dist = sqrtf(fmaf(rx, rx, fmaf(ry, ry, rz * rz)));
        float h[4];
        #pragma unroll
        for (int o = 0; o < 4; ++o) {
            float acc = sw[16 + o];
            acc = fmaf(sw[o * 4 + 0], rx, acc);
            acc = fmaf(sw[o * 4 + 1], ry, acc);
            acc = fmaf(sw[o * 4 + 2], rz, acc);
            acc = fmaf(sw[o * 4 + 3], dist, acc);
            h[o] = fmaxf(acc, 0.0f);
        }
        #pragma unroll
        for (int j = 0; j < 8; ++j) {
            float acc = sw[52 + j];
            acc = fmaf(sw[20 + j * 4 + 0], h[0], acc);
            acc = fmaf(sw[20 + j * 4 + 1], h[1], acc);
            acc = fmaf(sw[20 + j * 4 + 2], h[2], acc);
            acc = fmaf(sw[20 + j * 4 + 3], h[3], acc);
            out[p * 8 + j] = fmaxf(acc, 0.0f);
        }
    }
}

extern "C" void kernel_launch(void* const* d_in, const int* in_sizes, int n_in,
                              void* d_out, int out_size)
{
    const float* coords = (const float*)d_in[0];
    const float* nbr    = (const float*)d_in[1];
    const float* W1 = (const float*)d_in[2];
    const float* g1 = (const float*)d_in[3];
    const float* b1 = (const float*)d_in[4];
    const float* m1 = (const float*)d_in[5];
    const float* v1 = (const float*)d_in[6];
    const float* W2 = (const float*)d_in[7];
    const float* g2 = (const float*)d_in[8];
    const float* b2 = (const float*)d_in[9];
    const float* m2 = (const float*)d_in[10];
    const float* v2 = (const float*)d_in[11];
    float* out = (float*)d_out;

    int total_bn  = in_sizes[0] / 3;
    int total_bnk = total_bn * 16;

    lse_persist_kernel<<<NBLOCKS, 256>>>(coords, nbr,
                                         W1, g1, b1, m1, v1,
                                         W2, g2, b2, m2, v2,
                                         out, total_bnk);
}